// round 13
// baseline (speedup 1.0000x reference)
#include <cuda_runtime.h>
#include <cuda_fp16.h>
#include <cstdint>

#define B_DIM   1024
#define S_DIM   128
#define H_DIM   1024
#define V_DIM   50000
#define COPY_IDX 4
#define PAD_IDX  0
#define EPS_F    1e-10f

// GEMM tiling: CTA 128(M) x 256(N) x 32(K), 8 warps of 64x64, fp16 m16n8k16, f16 acc
#define TM 128
#define TN 256
#define NBLKS ((V_DIM + TN - 1) / TN)   // 196
#define PARTS (NBLKS * 4)               // 784 partial sums per row
#define KITERS (H_DIM / 32)             // 32
#define NSTAGE 3                        // 93KB smem -> 2 CTAs/SM

// smem layout (bytes). half rows padded to 40 halves (80B) for conflict-free ldmatrix.
#define SM_BIAS_B 0
#define SM_A_B    1024
#define A_STAGE_B (128 * 80)             // 10240
#define SM_B_B    (1024 + NSTAGE * A_STAGE_B)   // 31744
#define B_STAGE_B (256 * 80)             // 20480
#define SMEM_BYTES (SM_B_B + NSTAGE * B_STAGE_B)  // 93184

// ---------------- scratch ----------------
__device__ __half  g_logits[(size_t)B_DIM * V_DIM];    // 102.4 MB (fp16 logits)
__device__ __half2 g_Wh[(size_t)V_DIM * H_DIM / 2];    // 102.4 MB
__device__ __half2 g_hh[(size_t)B_DIM * H_DIM / 2];    // 2 MB
__device__ float   g_partial[(size_t)B_DIM * PARTS];   // 3.2 MB
__device__ float4  g_stats[B_DIM];                     // {0, 1/Z, copy, 1/norm}
__device__ int     g_tgt[B_DIM * S_DIM];
__device__ float   g_addval[B_DIM * S_DIM];

// ---------------- helpers ----------------
__device__ __forceinline__ uint32_t smem_u32(const void* p) {
    uint32_t a;
    asm("{ .reg .u64 t; cvta.to.shared.u64 t, %1; cvt.u32.u64 %0, t; }" : "=r"(a) : "l"(p));
    return a;
}
__device__ __forceinline__ void cp16(uint32_t dst, const void* src, int n) {
    asm volatile("cp.async.cg.shared.global [%0], [%1], 16, %2;\n" :: "r"(dst), "l"(src), "r"(n));
}
__device__ __forceinline__ void mma_f16acc(uint32_t* d, const uint32_t* a, const uint32_t* b) {
    asm volatile(
        "mma.sync.aligned.m16n8k16.row.col.f16.f16.f16.f16 "
        "{%0,%1},{%2,%3,%4,%5},{%6,%7},{%0,%1};\n"
        : "+r"(d[0]), "+r"(d[1])
        : "r"(a[0]), "r"(a[1]), "r"(a[2]), "r"(a[3]), "r"(b[0]), "r"(b[1]));
}
__device__ __forceinline__ void ldsm_x4(uint32_t* d, uint32_t a) {
    asm volatile("ldmatrix.sync.aligned.m8n8.x4.shared.b16 {%0,%1,%2,%3}, [%4];"
        : "=r"(d[0]), "=r"(d[1]), "=r"(d[2]), "=r"(d[3]) : "r"(a));
}
__device__ __forceinline__ void ldsm_x2(uint32_t* d, uint32_t a) {
    asm volatile("ldmatrix.sync.aligned.m8n8.x2.shared.b16 {%0,%1}, [%2];"
        : "=r"(d[0]), "=r"(d[1]) : "r"(a));
}
// int64-vs-int32 sniffing: int64 values < 2^31 have all odd 32-bit words zero.
__device__ __forceinline__ bool detect_i64(const int* p) {
    bool z = true;
#pragma unroll
    for (int i = 1; i < 32; i += 2) z = z && (p[i] == 0);
    return z;
}

// ---------------- K0: fp32 -> fp16 conversion ----------------
__global__ void __launch_bounds__(256)
convert_kernel(const float* __restrict__ W, const float* __restrict__ hidden)
{
    const size_t nW4 = (size_t)V_DIM * H_DIM / 4;
    const size_t nH4 = (size_t)B_DIM * H_DIM / 4;
    const size_t stride = (size_t)gridDim.x * blockDim.x;
    const float4* W4 = (const float4*)W;
    const float4* H4 = (const float4*)hidden;
    for (size_t i = blockIdx.x * blockDim.x + threadIdx.x; i < nW4; i += stride) {
        const float4 v = W4[i];
        g_Wh[2 * i]     = __floats2half2_rn(v.x, v.y);
        g_Wh[2 * i + 1] = __floats2half2_rn(v.z, v.w);
    }
    for (size_t i = blockIdx.x * blockDim.x + threadIdx.x; i < nH4; i += stride) {
        const float4 v = H4[i];
        g_hh[2 * i]     = __floats2half2_rn(v.x, v.y);
        g_hh[2 * i + 1] = __floats2half2_rn(v.z, v.w);
    }
}

// ---------------- K1: fp16 mma GEMM + fused exp row-partials ----------------
__device__ __forceinline__ void load_stage(uint32_t a_u32, uint32_t b_u32,
                                           int mBlk, int nBlk, int k0, int tid)
{
    const __half* Ah = (const __half*)g_hh;
    const __half* Bh = (const __half*)g_Wh;
#pragma unroll
    for (int j = 0; j < 6; ++j) {
        const int t = tid + j * 256;
        if (t < 512) {                       // A: 128 rows x 4 chunks of 8 halves
            const int row = t >> 2, q = t & 3;
            const __half* src = Ah + (size_t)(mBlk + row) * H_DIM + k0 + q * 8;
            cp16(a_u32 + row * 80 + q * 16, src, 16);
        } else {                             // B: 256 rows x 4 chunks
            const int t2 = t - 512;
            const int row = t2 >> 2, q = t2 & 3;
            const int gn = nBlk + row;
            const int ok = (gn < V_DIM) ? 16 : 0;
            const __half* src = Bh + (size_t)(ok ? gn : 0) * H_DIM + k0 + q * 8;
            cp16(b_u32 + row * 80 + q * 16, src, ok);
        }
    }
}

__global__ void __launch_bounds__(256, 2)
gemm_kernel(const float* __restrict__ bias)
{
    extern __shared__ float smf[];
    const uint32_t sb = smem_u32(smf);

    const int tid   = threadIdx.x;
    const int lane  = tid & 31;
    const int wid   = tid >> 5;
    const int warpM = wid & 1;       // 0..1
    const int warpN = wid >> 1;      // 0..3
    const int r     = lane >> 2;     // 0..7
    const int cq    = lane & 3;      // 0..3

    const int mBlk = blockIdx.x * TM;
    const int nBlk = blockIdx.y * TN;

    // bias preload
    {
        const int c = nBlk + tid;
        smf[tid] = (c < V_DIM) ? bias[c] : 0.f;
    }

    // ldmatrix per-lane base addresses (bytes)
    const uint32_t aBase = sb + SM_A_B +
        (uint32_t)(warpM * 64 + (lane & 15)) * 80 + (uint32_t)(lane >> 4) * 16;
    const uint32_t bBase = sb + SM_B_B +
        (uint32_t)(warpN * 64 + (lane & 7)) * 80 + (uint32_t)((lane >> 3) & 1) * 16;

    uint32_t acc[4][8][2];   // half2 accumulators
#pragma unroll
    for (int i = 0; i < 4; ++i)
#pragma unroll
        for (int j = 0; j < 8; ++j) { acc[i][j][0] = 0u; acc[i][j][1] = 0u; }

    // prologue: 2 stages
#pragma unroll
    for (int s = 0; s < NSTAGE - 1; ++s) {
        load_stage(sb + SM_A_B + s * A_STAGE_B, sb + SM_B_B + s * B_STAGE_B,
                   mBlk, nBlk, s * 32, tid);
        asm volatile("cp.async.commit_group;");
    }

    int sIdx = 0;   // stage slot of iteration ks
    for (int ks = 0; ks < KITERS; ++ks) {
        asm volatile("cp.async.wait_group 1;");
        __syncthreads();

        const uint32_t aStage = aBase + (uint32_t)(sIdx * A_STAGE_B);
        const uint32_t bStage = bBase + (uint32_t)(sIdx * B_STAGE_B);

#pragma unroll
        for (int sl = 0; sl < 2; ++sl) {
            uint32_t afr[4][4];
            uint32_t bfr[8][2];
#pragma unroll
            for (int mt = 0; mt < 4; ++mt)
                ldsm_x4(afr[mt], aStage + (uint32_t)(mt * 16 * 80 + sl * 32));
#pragma unroll
            for (int nt = 0; nt < 8; ++nt)
                ldsm_x2(bfr[nt], bStage + (uint32_t)(nt * 8 * 80 + sl * 32));
#pragma unroll
            for (int mt = 0; mt < 4; ++mt)
#pragma unroll
                for (int nt = 0; nt < 8; ++nt)
                    mma_f16acc(acc[mt][nt], afr[mt], bfr[nt]);
        }

        const int tl = ks + NSTAGE - 1;
        if (tl < KITERS) {
            int fillSlot = sIdx + (NSTAGE - 1);
            if (fillSlot >= NSTAGE) fillSlot -= NSTAGE;
            load_stage(sb + SM_A_B + fillSlot * A_STAGE_B,
                       sb + SM_B_B + fillSlot * B_STAGE_B,
                       mBlk, nBlk, tl * 32, tid);
        }
        asm volatile("cp.async.commit_group;");
        if (++sIdx == NSTAGE) sIdx = 0;
    }

    // epilogue: bias add (fp32), round-to-half store, exp partials from the
    // STORED half values (exact consistency with K3's reads).
    const float* bias_s = smf;
#pragma unroll
    for (int mt = 0; mt < 4; ++mt) {
        const int row0 = mBlk + warpM * 64 + mt * 16 + r;
        float rs0 = 0.f, rs1 = 0.f;
#pragma unroll
        for (int nt = 0; nt < 8; ++nt) {
            const int lc = warpN * 64 + nt * 8 + 2 * cq;
            const int gc = nBlk + lc;
            const float bv0 = bias_s[lc], bv1 = bias_s[lc + 1];
            const __half2 a01 = *(__half2*)&acc[mt][nt][0];
            const __half2 a23 = *(__half2*)&acc[mt][nt][1];
            const float v0 = __low2float(a01) + bv0;
            const float v1 = __high2float(a01) + bv1;
            const float v2 = __low2float(a23) + bv0;
            const float v3 = __high2float(a23) + bv1;
            if (gc < V_DIM) {   // V even, gc even => gc+1 < V too
                const __half2 s01 = __floats2half2_rn(v0, v1);
                const __half2 s23 = __floats2half2_rn(v2, v3);
                *(__half2*)&g_logits[(size_t)row0 * V_DIM + gc]       = s01;
                *(__half2*)&g_logits[(size_t)(row0 + 8) * V_DIM + gc] = s23;
                const float2 e01 = __half22float2(s01);
                const float2 e23 = __half22float2(s23);
                rs0 += __expf(e01.x) + __expf(e01.y);
                rs1 += __expf(e23.x) + __expf(e23.y);
            }
        }
        rs0 += __shfl_xor_sync(0xFFFFFFFF, rs0, 1);
        rs0 += __shfl_xor_sync(0xFFFFFFFF, rs0, 2);
        rs1 += __shfl_xor_sync(0xFFFFFFFF, rs1, 1);
        rs1 += __shfl_xor_sync(0xFFFFFFFF, rs1, 2);
        if (cq == 0) {
            const int pidx = blockIdx.y * 4 + warpN;
            g_partial[(size_t)row0 * PARTS + pidx]       = rs0;
            g_partial[(size_t)(row0 + 8) * PARTS + pidx] = rs1;
        }
    }
}

// ---------------- K2: stats (partials reduce + gather) ----------------
__global__ void __launch_bounds__(256)
stats_kernel(const float* __restrict__ attn,
             const void* __restrict__ src_raw,
             const void* __restrict__ alignment_raw)
{
    __shared__ float red[256];
    const int b   = blockIdx.x;
    const int tid = threadIdx.x;

    float s = 0.f;
    for (int i = tid; i < PARTS; i += 256) s += g_partial[(size_t)b * PARTS + i];
    red[tid] = s; __syncthreads();
    for (int st = 128; st > 0; st >>= 1) {
        if (tid < st) red[tid] += red[tid + st];
        __syncthreads();
    }
    const float Sraw = red[0];
    __syncthreads();

    const float l4 = __half2float(g_logits[(size_t)b * V_DIM + COPY_IDX]);
    const float Z  = Sraw - __expf(l4) + 1.0f;           // exp(1e-10) == 1.0f
    const float copy = 1.f / (1.f + __expf(-l4));

    const bool src64 = detect_i64((const int*)src_raw);
    const bool aln64 = detect_i64((const int*)alignment_raw);

    float av = 0.f, a0 = 0.f;
    if (tid < S_DIM) {
        const size_t sidx = (size_t)b * S_DIM + tid;
        long long sv;
        if (src64) sv = ((const long long*)src_raw)[sidx];
        else       sv = (long long)((const int*)src_raw)[sidx];
        int tg;
        if (aln64) tg = (int)((const long long*)alignment_raw)[sv];
        else       tg = ((const int*)alignment_raw)[sv];
        g_tgt[b * S_DIM + tid] = tg;
        const float a = attn[sidx];
        g_addval[b * S_DIM + tid] = a * copy;
        av = a;
        a0 = (tg == PAD_IDX) ? a : 0.f;
    }
    red[tid] = av; __syncthreads();
    for (int st = 128; st > 0; st >>= 1) {
        if (tid < st) red[tid] += red[tid + st];
        __syncthreads();
    }
    const float sumattn = red[0];
    __syncthreads();
    red[tid] = a0; __syncthreads();
    for (int st = 128; st > 0; st >>= 1) {
        if (tid < st) red[tid] += red[tid + st];
        __syncthreads();
    }
    const float scat0 = red[0];

    if (tid == 0) {
        const float l0 = __half2float(g_logits[(size_t)b * V_DIM + PAD_IDX]);
        const float prepad = (1.f - copy) * __expf(l0) / Z + copy * scat0;
        const float norm = (1.f - copy) + copy * sumattn - prepad + EPS_F;
        g_stats[b] = make_float4(0.f, 1.f / Z, copy, 1.f / norm);
    }
}

// ---------------- K3: streaming log-prob:  out = log(k) + logit ----------------
// One block per row (grid 1024) => ~1 wave at 8 blocks/SM; each thread strides
// 24 uint4 iterations. k*e^x >= ~4e-7 >> eps, so log(k e^x + eps) = log k + x.
__global__ void __launch_bounds__(256)
final_stream_kernel(float* __restrict__ out)
{
    const int b = blockIdx.x;
    const float4 st = g_stats[b];
    const float invZ = st.y, copy = st.z, invnorm = st.w;
    const float logk = __logf((1.f - copy) * invZ * invnorm);
    const uint4* in8 = (const uint4*)(g_logits + (size_t)b * V_DIM);  // 8 halves each
    float4* out4 = (float4*)(out + (size_t)b * V_DIM);
    const int NV8 = V_DIM / 8;                 // 6250
    for (int i = threadIdx.x; i < NV8; i += 256) {
        const uint4 u = in8[i];
        const float2 p0 = __half22float2(*(const __half2*)&u.x);
        const float2 p1 = __half22float2(*(const __half2*)&u.y);
        float2 p2 = __half22float2(*(const __half2*)&u.z);
        const float2 p3 = __half22float2(*(const __half2*)&u.w);
        if (i == 0) p2.x = 1e-10f;             // COPY (element 4)
        float4 r0, r1;
        r0.x = logk + p0.x;
        r0.y = logk + p0.y;
        r0.z = logk + p1.x;
        r0.w = logk + p1.y;
        r1.x = logk + p2.x;
        r1.y = logk + p2.y;
        r1.z = logk + p3.x;
        r1.w = logk + p3.y;
        if (i == 0) r0.x = __logf(EPS_F * invnorm + EPS_F);   // PAD (exact)
        __stcs(&out4[2 * i],     r0);
        __stcs(&out4[2 * i + 1], r1);
    }
}

// ---------------- K4: scatter fixup (<=128 positions/row, dup-aggregating) --
__global__ void __launch_bounds__(128)
fixup_kernel(float* __restrict__ out)
{
    __shared__ int   stg[S_DIM];
    __shared__ float sad[S_DIM];
    const int b = blockIdx.x, t = threadIdx.x;
    stg[t] = g_tgt[b * S_DIM + t];
    sad[t] = g_addval[b * S_DIM + t];
    __syncthreads();
    const int tg = stg[t];
    if (tg == PAD_IDX) return;
    float tot = 0.f; bool first = true;
    for (int j = 0; j < S_DIM; ++j) {
        if (stg[j] == tg) { tot += sad[j]; if (j < t) first = false; }
    }
    if (!first) return;
    const float4 st = g_stats[b];
    const float l = (tg == COPY_IDX) ? 1e-10f
                                     : __half2float(g_logits[(size_t)b * V_DIM + tg]);
    const float p = (1.f - st.z) * st.y * __expf(l) + tot;
    out[(size_t)b * V_DIM + tg] = __logf(p * st.w + EPS_F);
}

// ---------------- launch ----------------
extern "C" void kernel_launch(void* const* d_in, const int* in_sizes, int n_in,
                              void* d_out, int out_size)
{
    const float* hidden    = (const float*)d_in[0];
    const void*  src       = d_in[1];
    const float* attn      = (const float*)d_in[2];
    const float* W         = (const float*)d_in[3];
    const float* bias      = (const float*)d_in[4];
    const void*  alignment = d_in[5];
    float*       out       = (float*)d_out;

    cudaFuncSetAttribute(gemm_kernel, cudaFuncAttributeMaxDynamicSharedMemorySize, SMEM_BYTES);

    convert_kernel<<<1184, 256>>>(W, hidden);

    dim3 g1(B_DIM / TM, NBLKS);                  // (8, 196) — M fastest for W L2 reuse
    gemm_kernel<<<g1, 256, SMEM_BYTES>>>(bias);

    stats_kernel<<<B_DIM, 256>>>(attn, src, alignment);

    final_stream_kernel<<<B_DIM, 256>>>(out);

    fixup_kernel<<<B_DIM, S_DIM>>>(out);
}

// round 14
// speedup vs baseline: 1.0112x; 1.0112x over previous
#include <cuda_runtime.h>
#include <cuda_fp16.h>
#include <cstdint>

#define B_DIM   1024
#define S_DIM   128
#define H_DIM   1024
#define V_DIM   50000
#define COPY_IDX 4
#define PAD_IDX  0
#define EPS_F    1e-10f

// GEMM tiling: CTA 128(M) x 256(N) x 32(K), 8 warps of 64x64, fp16 m16n8k16, f16 acc
#define TM 128
#define TN 256
#define NBLKS ((V_DIM + TN - 1) / TN)   // 196
#define PARTS (NBLKS * 4)               // 784 partial sums per row
#define KITERS (H_DIM / 32)             // 32
#define NSTAGE 3                        // 93KB smem -> 2 CTAs/SM

// smem layout (bytes). half rows padded to 40 halves (80B) for conflict-free ldmatrix.
#define SM_BIAS_B 0
#define SM_A_B    1024
#define A_STAGE_B (128 * 80)             // 10240
#define SM_B_B    (1024 + NSTAGE * A_STAGE_B)   // 31744
#define B_STAGE_B (256 * 80)             // 20480
#define SMEM_BYTES (SM_B_B + NSTAGE * B_STAGE_B)  // 93184

// ---------------- scratch ----------------
__device__ __half  g_logits[(size_t)B_DIM * V_DIM];    // 102.4 MB (fp16 logits)
__device__ __half2 g_Wh[(size_t)V_DIM * H_DIM / 2];    // 102.4 MB
__device__ __half2 g_hh[(size_t)B_DIM * H_DIM / 2];    // 2 MB
__device__ float   g_partial[(size_t)B_DIM * PARTS];   // 3.2 MB
__device__ float4  g_stats[B_DIM];                     // {0, 1/Z, copy, 1/norm}
__device__ int     g_tgt[B_DIM * S_DIM];
__device__ float   g_addval[B_DIM * S_DIM];

// ---------------- helpers ----------------
__device__ __forceinline__ uint32_t smem_u32(const void* p) {
    uint32_t a;
    asm("{ .reg .u64 t; cvta.to.shared.u64 t, %1; cvt.u32.u64 %0, t; }" : "=r"(a) : "l"(p));
    return a;
}
__device__ __forceinline__ void cp16(uint32_t dst, const void* src, int n) {
    asm volatile("cp.async.cg.shared.global [%0], [%1], 16, %2;\n" :: "r"(dst), "l"(src), "r"(n));
}
__device__ __forceinline__ void mma_f16acc(uint32_t* d, const uint32_t* a, const uint32_t* b) {
    asm volatile(
        "mma.sync.aligned.m16n8k16.row.col.f16.f16.f16.f16 "
        "{%0,%1},{%2,%3,%4,%5},{%6,%7},{%0,%1};\n"
        : "+r"(d[0]), "+r"(d[1])
        : "r"(a[0]), "r"(a[1]), "r"(a[2]), "r"(a[3]), "r"(b[0]), "r"(b[1]));
}
__device__ __forceinline__ void ldsm_x4(uint32_t* d, uint32_t a) {
    asm volatile("ldmatrix.sync.aligned.m8n8.x4.shared.b16 {%0,%1,%2,%3}, [%4];"
        : "=r"(d[0]), "=r"(d[1]), "=r"(d[2]), "=r"(d[3]) : "r"(a));
}
__device__ __forceinline__ void ldsm_x2(uint32_t* d, uint32_t a) {
    asm volatile("ldmatrix.sync.aligned.m8n8.x2.shared.b16 {%0,%1}, [%2];"
        : "=r"(d[0]), "=r"(d[1]) : "r"(a));
}
// int64-vs-int32 sniffing: int64 values < 2^31 have all odd 32-bit words zero.
__device__ __forceinline__ bool detect_i64(const int* p) {
    bool z = true;
#pragma unroll
    for (int i = 1; i < 32; i += 2) z = z && (p[i] == 0);
    return z;
}

// ---------------- K0: fp32 -> fp16 conversion ----------------
__global__ void __launch_bounds__(256)
convert_kernel(const float* __restrict__ W, const float* __restrict__ hidden)
{
    const size_t nW4 = (size_t)V_DIM * H_DIM / 4;
    const size_t nH4 = (size_t)B_DIM * H_DIM / 4;
    const size_t stride = (size_t)gridDim.x * blockDim.x;
    const float4* W4 = (const float4*)W;
    const float4* H4 = (const float4*)hidden;
    for (size_t i = blockIdx.x * blockDim.x + threadIdx.x; i < nW4; i += stride) {
        const float4 v = W4[i];
        g_Wh[2 * i]     = __floats2half2_rn(v.x, v.y);
        g_Wh[2 * i + 1] = __floats2half2_rn(v.z, v.w);
    }
    for (size_t i = blockIdx.x * blockDim.x + threadIdx.x; i < nH4; i += stride) {
        const float4 v = H4[i];
        g_hh[2 * i]     = __floats2half2_rn(v.x, v.y);
        g_hh[2 * i + 1] = __floats2half2_rn(v.z, v.w);
    }
}

// ---------------- K1: fp16 mma GEMM + fused exp row-partials ----------------
__device__ __forceinline__ void load_stage(uint32_t a_u32, uint32_t b_u32,
                                           int mBlk, int nBlk, int k0, int tid)
{
    const __half* Ah = (const __half*)g_hh;
    const __half* Bh = (const __half*)g_Wh;
#pragma unroll
    for (int j = 0; j < 6; ++j) {
        const int t = tid + j * 256;
        if (t < 512) {                       // A: 128 rows x 4 chunks of 8 halves
            const int row = t >> 2, q = t & 3;
            const __half* src = Ah + (size_t)(mBlk + row) * H_DIM + k0 + q * 8;
            cp16(a_u32 + row * 80 + q * 16, src, 16);
        } else {                             // B: 256 rows x 4 chunks
            const int t2 = t - 512;
            const int row = t2 >> 2, q = t2 & 3;
            const int gn = nBlk + row;
            const int ok = (gn < V_DIM) ? 16 : 0;
            const __half* src = Bh + (size_t)(ok ? gn : 0) * H_DIM + k0 + q * 8;
            cp16(b_u32 + row * 80 + q * 16, src, ok);
        }
    }
}

__global__ void __launch_bounds__(256, 2)
gemm_kernel(const float* __restrict__ bias)
{
    extern __shared__ float smf[];
    const uint32_t sb = smem_u32(smf);

    const int tid   = threadIdx.x;
    const int lane  = tid & 31;
    const int wid   = tid >> 5;
    const int warpM = wid & 1;       // 0..1
    const int warpN = wid >> 1;      // 0..3
    const int r     = lane >> 2;     // 0..7
    const int cq    = lane & 3;      // 0..3

    const int mBlk = blockIdx.x * TM;
    const int nBlk = blockIdx.y * TN;

    // bias preload
    {
        const int c = nBlk + tid;
        smf[tid] = (c < V_DIM) ? bias[c] : 0.f;
    }

    // ldmatrix per-lane base addresses (bytes)
    const uint32_t aBase = sb + SM_A_B +
        (uint32_t)(warpM * 64 + (lane & 15)) * 80 + (uint32_t)(lane >> 4) * 16;
    const uint32_t bBase = sb + SM_B_B +
        (uint32_t)(warpN * 64 + (lane & 7)) * 80 + (uint32_t)((lane >> 3) & 1) * 16;

    uint32_t acc[4][8][2];   // half2 accumulators
#pragma unroll
    for (int i = 0; i < 4; ++i)
#pragma unroll
        for (int j = 0; j < 8; ++j) { acc[i][j][0] = 0u; acc[i][j][1] = 0u; }

    // prologue: 2 stages
#pragma unroll
    for (int s = 0; s < NSTAGE - 1; ++s) {
        load_stage(sb + SM_A_B + s * A_STAGE_B, sb + SM_B_B + s * B_STAGE_B,
                   mBlk, nBlk, s * 32, tid);
        asm volatile("cp.async.commit_group;");
    }

    int sIdx = 0;   // stage slot of iteration ks
    for (int ks = 0; ks < KITERS; ++ks) {
        asm volatile("cp.async.wait_group 1;");
        __syncthreads();

        const uint32_t aStage = aBase + (uint32_t)(sIdx * A_STAGE_B);
        const uint32_t bStage = bBase + (uint32_t)(sIdx * B_STAGE_B);

#pragma unroll
        for (int sl = 0; sl < 2; ++sl) {
            uint32_t afr[4][4];
            uint32_t bfr[8][2];
#pragma unroll
            for (int mt = 0; mt < 4; ++mt)
                ldsm_x4(afr[mt], aStage + (uint32_t)(mt * 16 * 80 + sl * 32));
#pragma unroll
            for (int nt = 0; nt < 8; ++nt)
                ldsm_x2(bfr[nt], bStage + (uint32_t)(nt * 8 * 80 + sl * 32));
#pragma unroll
            for (int mt = 0; mt < 4; ++mt)
#pragma unroll
                for (int nt = 0; nt < 8; ++nt)
                    mma_f16acc(acc[mt][nt], afr[mt], bfr[nt]);
        }

        const int tl = ks + NSTAGE - 1;
        if (tl < KITERS) {
            int fillSlot = sIdx + (NSTAGE - 1);
            if (fillSlot >= NSTAGE) fillSlot -= NSTAGE;
            load_stage(sb + SM_A_B + fillSlot * A_STAGE_B,
                       sb + SM_B_B + fillSlot * B_STAGE_B,
                       mBlk, nBlk, tl * 32, tid);
        }
        asm volatile("cp.async.commit_group;");
        if (++sIdx == NSTAGE) sIdx = 0;
    }

    // epilogue: bias add (fp32), round-to-half store, exp partials from the
    // STORED half values (exact consistency with K3's reads).
    const float* bias_s = smf;
#pragma unroll
    for (int mt = 0; mt < 4; ++mt) {
        const int row0 = mBlk + warpM * 64 + mt * 16 + r;
        float rs0 = 0.f, rs1 = 0.f;
#pragma unroll
        for (int nt = 0; nt < 8; ++nt) {
            const int lc = warpN * 64 + nt * 8 + 2 * cq;
            const int gc = nBlk + lc;
            const float bv0 = bias_s[lc], bv1 = bias_s[lc + 1];
            const __half2 a01 = *(__half2*)&acc[mt][nt][0];
            const __half2 a23 = *(__half2*)&acc[mt][nt][1];
            const float v0 = __low2float(a01) + bv0;
            const float v1 = __high2float(a01) + bv1;
            const float v2 = __low2float(a23) + bv0;
            const float v3 = __high2float(a23) + bv1;
            if (gc < V_DIM) {   // V even, gc even => gc+1 < V too
                const __half2 s01 = __floats2half2_rn(v0, v1);
                const __half2 s23 = __floats2half2_rn(v2, v3);
                *(__half2*)&g_logits[(size_t)row0 * V_DIM + gc]       = s01;
                *(__half2*)&g_logits[(size_t)(row0 + 8) * V_DIM + gc] = s23;
                const float2 e01 = __half22float2(s01);
                const float2 e23 = __half22float2(s23);
                rs0 += __expf(e01.x) + __expf(e01.y);
                rs1 += __expf(e23.x) + __expf(e23.y);
            }
        }
        rs0 += __shfl_xor_sync(0xFFFFFFFF, rs0, 1);
        rs0 += __shfl_xor_sync(0xFFFFFFFF, rs0, 2);
        rs1 += __shfl_xor_sync(0xFFFFFFFF, rs1, 1);
        rs1 += __shfl_xor_sync(0xFFFFFFFF, rs1, 2);
        if (cq == 0) {
            const int pidx = blockIdx.y * 4 + warpN;
            g_partial[(size_t)row0 * PARTS + pidx]       = rs0;
            g_partial[(size_t)(row0 + 8) * PARTS + pidx] = rs1;
        }
    }
}

// ---------------- K2: stats (partials reduce + gather) ----------------
__global__ void __launch_bounds__(256)
stats_kernel(const float* __restrict__ attn,
             const void* __restrict__ src_raw,
             const void* __restrict__ alignment_raw)
{
    __shared__ float red[256];
    const int b   = blockIdx.x;
    const int tid = threadIdx.x;

    float s = 0.f;
    for (int i = tid; i < PARTS; i += 256) s += g_partial[(size_t)b * PARTS + i];
    red[tid] = s; __syncthreads();
    for (int st = 128; st > 0; st >>= 1) {
        if (tid < st) red[tid] += red[tid + st];
        __syncthreads();
    }
    const float Sraw = red[0];
    __syncthreads();

    const float l4 = __half2float(g_logits[(size_t)b * V_DIM + COPY_IDX]);
    const float Z  = Sraw - __expf(l4) + 1.0f;           // exp(1e-10) == 1.0f
    const float copy = 1.f / (1.f + __expf(-l4));

    const bool src64 = detect_i64((const int*)src_raw);
    const bool aln64 = detect_i64((const int*)alignment_raw);

    float av = 0.f, a0 = 0.f;
    if (tid < S_DIM) {
        const size_t sidx = (size_t)b * S_DIM + tid;
        long long sv;
        if (src64) sv = ((const long long*)src_raw)[sidx];
        else       sv = (long long)((const int*)src_raw)[sidx];
        int tg;
        if (aln64) tg = (int)((const long long*)alignment_raw)[sv];
        else       tg = ((const int*)alignment_raw)[sv];
        g_tgt[b * S_DIM + tid] = tg;
        const float a = attn[sidx];
        g_addval[b * S_DIM + tid] = a * copy;
        av = a;
        a0 = (tg == PAD_IDX) ? a : 0.f;
    }
    red[tid] = av; __syncthreads();
    for (int st = 128; st > 0; st >>= 1) {
        if (tid < st) red[tid] += red[tid + st];
        __syncthreads();
    }
    const float sumattn = red[0];
    __syncthreads();
    red[tid] = a0; __syncthreads();
    for (int st = 128; st > 0; st >>= 1) {
        if (tid < st) red[tid] += red[tid + st];
        __syncthreads();
    }
    const float scat0 = red[0];

    if (tid == 0) {
        const float l0 = __half2float(g_logits[(size_t)b * V_DIM + PAD_IDX]);
        const float prepad = (1.f - copy) * __expf(l0) / Z + copy * scat0;
        const float norm = (1.f - copy) + copy * sumattn - prepad + EPS_F;
        g_stats[b] = make_float4(0.f, 1.f / Z, copy, 1.f / norm);
    }
}

// ---------------- K3: streaming log-prob:  out = log(k) + logit ----------------
// grid (1024, 8); each thread handles TWO uint4s per trip for 2x memory-level
// parallelism. k*e^x >= ~4e-7 >> eps, so log(k e^x + eps) = log k + x.
#define K3_SPLIT 8
__global__ void __launch_bounds__(256)
final_stream_kernel(float* __restrict__ out)
{
    const int b = blockIdx.x;
    const float4 st = g_stats[b];
    const float invZ = st.y, copy = st.z, invnorm = st.w;
    const float logk = __logf((1.f - copy) * invZ * invnorm);
    const uint4* in8 = (const uint4*)(g_logits + (size_t)b * V_DIM);  // 8 halves each
    float4* out4 = (float4*)(out + (size_t)b * V_DIM);
    const int NV8 = V_DIM / 8;                 // 6250
    const int per = (NV8 + K3_SPLIT - 1) / K3_SPLIT;   // 782
    const int beg = blockIdx.y * per;
    const int end = (beg + per < NV8) ? beg + per : NV8;

    for (int i0 = beg + threadIdx.x; i0 < end; i0 += 512) {
        const int i1 = i0 + 256;
        const bool ok1 = (i1 < end);
        const uint4 ua = in8[i0];
        uint4 ub;
        if (ok1) ub = in8[i1];

#pragma unroll
        for (int half = 0; half < 2; ++half) {
            const int  i = half ? i1 : i0;
            const uint4 u = half ? ub : ua;
            if (half && !ok1) break;
            const float2 p0 = __half22float2(*(const __half2*)&u.x);
            const float2 p1 = __half22float2(*(const __half2*)&u.y);
            float2 p2 = __half22float2(*(const __half2*)&u.z);
            const float2 p3 = __half22float2(*(const __half2*)&u.w);
            if (i == 0) p2.x = 1e-10f;             // COPY (element 4)
            float4 r0, r1;
            r0.x = logk + p0.x;
            r0.y = logk + p0.y;
            r0.z = logk + p1.x;
            r0.w = logk + p1.y;
            r1.x = logk + p2.x;
            r1.y = logk + p2.y;
            r1.z = logk + p3.x;
            r1.w = logk + p3.y;
            if (i == 0) r0.x = __logf(EPS_F * invnorm + EPS_F);   // PAD (exact)
            __stcs(&out4[2 * i],     r0);
            __stcs(&out4[2 * i + 1], r1);
        }
    }
}

// ---------------- K4: scatter fixup (<=128 positions/row, dup-aggregating) --
__global__ void __launch_bounds__(128)
fixup_kernel(float* __restrict__ out)
{
    __shared__ int   stg[S_DIM];
    __shared__ float sad[S_DIM];
    const int b = blockIdx.x, t = threadIdx.x;
    stg[t] = g_tgt[b * S_DIM + t];
    sad[t] = g_addval[b * S_DIM + t];
    __syncthreads();
    const int tg = stg[t];
    if (tg == PAD_IDX) return;
    float tot = 0.f; bool first = true;
    for (int j = 0; j < S_DIM; ++j) {
        if (stg[j] == tg) { tot += sad[j]; if (j < t) first = false; }
    }
    if (!first) return;
    const float4 st = g_stats[b];
    const float l = (tg == COPY_IDX) ? 1e-10f
                                     : __half2float(g_logits[(size_t)b * V_DIM + tg]);
    const float p = (1.f - st.z) * st.y * __expf(l) + tot;
    out[(size_t)b * V_DIM + tg] = __logf(p * st.w + EPS_F);
}

// ---------------- launch ----------------
extern "C" void kernel_launch(void* const* d_in, const int* in_sizes, int n_in,
                              void* d_out, int out_size)
{
    const float* hidden    = (const float*)d_in[0];
    const void*  src       = d_in[1];
    const float* attn      = (const float*)d_in[2];
    const float* W         = (const float*)d_in[3];
    const float* bias      = (const float*)d_in[4];
    const void*  alignment = d_in[5];
    float*       out       = (float*)d_out;

    cudaFuncSetAttribute(gemm_kernel, cudaFuncAttributeMaxDynamicSharedMemorySize, SMEM_BYTES);

    convert_kernel<<<2368, 256>>>(W, hidden);

    dim3 g1(B_DIM / TM, NBLKS);                  // (8, 196) — M fastest for W L2 reuse
    gemm_kernel<<<g1, 256, SMEM_BYTES>>>(bias);

    stats_kernel<<<B_DIM, 256>>>(attn, src, alignment);

    dim3 g3(B_DIM, K3_SPLIT);
    final_stream_kernel<<<g3, 256>>>(out);

    fixup_kernel<<<B_DIM, S_DIM>>>(out);
}

// round 15
// speedup vs baseline: 1.0250x; 1.0137x over previous
#include <cuda_runtime.h>
#include <cuda_fp16.h>
#include <cstdint>

#define B_DIM   1024
#define S_DIM   128
#define H_DIM   1024
#define V_DIM   50000
#define COPY_IDX 4
#define PAD_IDX  0
#define EPS_F    1e-10f

// GEMM tiling: CTA 128(M) x 256(N) x 32(K), 8 warps of 64x64, fp16 m16n8k16, f16 acc
#define TM 128
#define TN 256
#define NBLKS ((V_DIM + TN - 1) / TN)   // 196
#define PARTS (NBLKS * 4)               // 784 partial sums per row
#define KITERS (H_DIM / 32)             // 32
#define NSTAGE 3                        // 93KB smem -> 2 CTAs/SM

// smem layout (bytes). half rows padded to 40 halves (80B) for conflict-free ldmatrix.
#define SM_BIAS_B 0
#define SM_A_B    1024
#define A_STAGE_B (128 * 80)             // 10240
#define SM_B_B    (1024 + NSTAGE * A_STAGE_B)   // 31744
#define B_STAGE_B (256 * 80)             // 20480
#define SMEM_BYTES (SM_B_B + NSTAGE * B_STAGE_B)  // 93184

// ---------------- scratch ----------------
__device__ __half  g_logits[(size_t)B_DIM * V_DIM];    // 102.4 MB (fp16 logits)
__device__ __half2 g_Wh[(size_t)V_DIM * H_DIM / 2];    // 102.4 MB
__device__ __half2 g_hh[(size_t)B_DIM * H_DIM / 2];    // 2 MB
__device__ float   g_partial[(size_t)B_DIM * PARTS];   // 3.2 MB
__device__ float4  g_stats[B_DIM];                     // {0, 1/Z, copy, 1/norm}
__device__ int     g_tgt[B_DIM * S_DIM];
__device__ float   g_addval[B_DIM * S_DIM];

// ---------------- helpers ----------------
__device__ __forceinline__ uint32_t smem_u32(const void* p) {
    uint32_t a;
    asm("{ .reg .u64 t; cvta.to.shared.u64 t, %1; cvt.u32.u64 %0, t; }" : "=r"(a) : "l"(p));
    return a;
}
__device__ __forceinline__ void cp16(uint32_t dst, const void* src, int n) {
    asm volatile("cp.async.cg.shared.global [%0], [%1], 16, %2;\n" :: "r"(dst), "l"(src), "r"(n));
}
__device__ __forceinline__ void mma_f16acc(uint32_t* d, const uint32_t* a, const uint32_t* b) {
    asm volatile(
        "mma.sync.aligned.m16n8k16.row.col.f16.f16.f16.f16 "
        "{%0,%1},{%2,%3,%4,%5},{%6,%7},{%0,%1};\n"
        : "+r"(d[0]), "+r"(d[1])
        : "r"(a[0]), "r"(a[1]), "r"(a[2]), "r"(a[3]), "r"(b[0]), "r"(b[1]));
}
__device__ __forceinline__ void ldsm_x4(uint32_t* d, uint32_t a) {
    asm volatile("ldmatrix.sync.aligned.m8n8.x4.shared.b16 {%0,%1,%2,%3}, [%4];"
        : "=r"(d[0]), "=r"(d[1]), "=r"(d[2]), "=r"(d[3]) : "r"(a));
}
__device__ __forceinline__ void ldsm_x2(uint32_t* d, uint32_t a) {
    asm volatile("ldmatrix.sync.aligned.m8n8.x2.shared.b16 {%0,%1}, [%2];"
        : "=r"(d[0]), "=r"(d[1]) : "r"(a));
}
// int64-vs-int32 sniffing: int64 values < 2^31 have all odd 32-bit words zero.
__device__ __forceinline__ bool detect_i64(const int* p) {
    bool z = true;
#pragma unroll
    for (int i = 1; i < 32; i += 2) z = z && (p[i] == 0);
    return z;
}

// ---------------- K0: fp32 -> fp16 conversion ----------------
__global__ void __launch_bounds__(256)
convert_kernel(const float* __restrict__ W, const float* __restrict__ hidden)
{
    const size_t nW4 = (size_t)V_DIM * H_DIM / 4;
    const size_t nH4 = (size_t)B_DIM * H_DIM / 4;
    const size_t stride = (size_t)gridDim.x * blockDim.x;
    const float4* W4 = (const float4*)W;
    const float4* H4 = (const float4*)hidden;
    for (size_t i = blockIdx.x * blockDim.x + threadIdx.x; i < nW4; i += stride) {
        const float4 v = W4[i];
        g_Wh[2 * i]     = __floats2half2_rn(v.x, v.y);
        g_Wh[2 * i + 1] = __floats2half2_rn(v.z, v.w);
    }
    for (size_t i = blockIdx.x * blockDim.x + threadIdx.x; i < nH4; i += stride) {
        const float4 v = H4[i];
        g_hh[2 * i]     = __floats2half2_rn(v.x, v.y);
        g_hh[2 * i + 1] = __floats2half2_rn(v.z, v.w);
    }
}

// ---------------- K1: fp16 mma GEMM + fused exp row-partials ----------------
__device__ __forceinline__ void load_stage(uint32_t a_u32, uint32_t b_u32,
                                           int mBlk, int nBlk, int k0, int tid)
{
    const __half* Ah = (const __half*)g_hh;
    const __half* Bh = (const __half*)g_Wh;
#pragma unroll
    for (int j = 0; j < 6; ++j) {
        const int t = tid + j * 256;
        if (t < 512) {                       // A: 128 rows x 4 chunks of 8 halves
            const int row = t >> 2, q = t & 3;
            const __half* src = Ah + (size_t)(mBlk + row) * H_DIM + k0 + q * 8;
            cp16(a_u32 + row * 80 + q * 16, src, 16);
        } else {                             // B: 256 rows x 4 chunks
            const int t2 = t - 512;
            const int row = t2 >> 2, q = t2 & 3;
            const int gn = nBlk + row;
            const int ok = (gn < V_DIM) ? 16 : 0;
            const __half* src = Bh + (size_t)(ok ? gn : 0) * H_DIM + k0 + q * 8;
            cp16(b_u32 + row * 80 + q * 16, src, ok);
        }
    }
}

__global__ void __launch_bounds__(256, 2)
gemm_kernel(const float* __restrict__ bias)
{
    extern __shared__ float smf[];
    const uint32_t sb = smem_u32(smf);

    const int tid   = threadIdx.x;
    const int lane  = tid & 31;
    const int wid   = tid >> 5;
    const int warpM = wid & 1;       // 0..1
    const int warpN = wid >> 1;      // 0..3
    const int r     = lane >> 2;     // 0..7
    const int cq    = lane & 3;      // 0..3

    const int mBlk = blockIdx.x * TM;
    const int nBlk = blockIdx.y * TN;

    // bias preload
    {
        const int c = nBlk + tid;
        smf[tid] = (c < V_DIM) ? bias[c] : 0.f;
    }

    // ldmatrix per-lane base addresses (bytes)
    const uint32_t aBase = sb + SM_A_B +
        (uint32_t)(warpM * 64 + (lane & 15)) * 80 + (uint32_t)(lane >> 4) * 16;
    const uint32_t bBase = sb + SM_B_B +
        (uint32_t)(warpN * 64 + (lane & 7)) * 80 + (uint32_t)((lane >> 3) & 1) * 16;

    uint32_t acc[4][8][2];   // half2 accumulators
#pragma unroll
    for (int i = 0; i < 4; ++i)
#pragma unroll
        for (int j = 0; j < 8; ++j) { acc[i][j][0] = 0u; acc[i][j][1] = 0u; }

    // prologue: 2 stages
#pragma unroll
    for (int s = 0; s < NSTAGE - 1; ++s) {
        load_stage(sb + SM_A_B + s * A_STAGE_B, sb + SM_B_B + s * B_STAGE_B,
                   mBlk, nBlk, s * 32, tid);
        asm volatile("cp.async.commit_group;");
    }

    int sIdx = 0;   // stage slot of iteration ks
    for (int ks = 0; ks < KITERS; ++ks) {
        asm volatile("cp.async.wait_group 1;");
        __syncthreads();

        const uint32_t aStage = aBase + (uint32_t)(sIdx * A_STAGE_B);
        const uint32_t bStage = bBase + (uint32_t)(sIdx * B_STAGE_B);

#pragma unroll
        for (int sl = 0; sl < 2; ++sl) {
            uint32_t afr[4][4];
            uint32_t bfr[8][2];
#pragma unroll
            for (int mt = 0; mt < 4; ++mt)
                ldsm_x4(afr[mt], aStage + (uint32_t)(mt * 16 * 80 + sl * 32));
#pragma unroll
            for (int nt = 0; nt < 8; ++nt)
                ldsm_x2(bfr[nt], bStage + (uint32_t)(nt * 8 * 80 + sl * 32));
#pragma unroll
            for (int mt = 0; mt < 4; ++mt)
#pragma unroll
                for (int nt = 0; nt < 8; ++nt)
                    mma_f16acc(acc[mt][nt], afr[mt], bfr[nt]);
        }

        const int tl = ks + NSTAGE - 1;
        if (tl < KITERS) {
            int fillSlot = sIdx + (NSTAGE - 1);
            if (fillSlot >= NSTAGE) fillSlot -= NSTAGE;
            load_stage(sb + SM_A_B + fillSlot * A_STAGE_B,
                       sb + SM_B_B + fillSlot * B_STAGE_B,
                       mBlk, nBlk, tl * 32, tid);
        }
        asm volatile("cp.async.commit_group;");
        if (++sIdx == NSTAGE) sIdx = 0;
    }

    // epilogue: bias add (fp32), round-to-half store, exp partials from the
    // STORED half values (exact consistency with K3's reads).
    const float* bias_s = smf;
#pragma unroll
    for (int mt = 0; mt < 4; ++mt) {
        const int row0 = mBlk + warpM * 64 + mt * 16 + r;
        float rs0 = 0.f, rs1 = 0.f;
#pragma unroll
        for (int nt = 0; nt < 8; ++nt) {
            const int lc = warpN * 64 + nt * 8 + 2 * cq;
            const int gc = nBlk + lc;
            const float bv0 = bias_s[lc], bv1 = bias_s[lc + 1];
            const __half2 a01 = *(__half2*)&acc[mt][nt][0];
            const __half2 a23 = *(__half2*)&acc[mt][nt][1];
            const float v0 = __low2float(a01) + bv0;
            const float v1 = __high2float(a01) + bv1;
            const float v2 = __low2float(a23) + bv0;
            const float v3 = __high2float(a23) + bv1;
            if (gc < V_DIM) {   // V even, gc even => gc+1 < V too
                const __half2 s01 = __floats2half2_rn(v0, v1);
                const __half2 s23 = __floats2half2_rn(v2, v3);
                *(__half2*)&g_logits[(size_t)row0 * V_DIM + gc]       = s01;
                *(__half2*)&g_logits[(size_t)(row0 + 8) * V_DIM + gc] = s23;
                const float2 e01 = __half22float2(s01);
                const float2 e23 = __half22float2(s23);
                rs0 += __expf(e01.x) + __expf(e01.y);
                rs1 += __expf(e23.x) + __expf(e23.y);
            }
        }
        rs0 += __shfl_xor_sync(0xFFFFFFFF, rs0, 1);
        rs0 += __shfl_xor_sync(0xFFFFFFFF, rs0, 2);
        rs1 += __shfl_xor_sync(0xFFFFFFFF, rs1, 1);
        rs1 += __shfl_xor_sync(0xFFFFFFFF, rs1, 2);
        if (cq == 0) {
            const int pidx = blockIdx.y * 4 + warpN;
            g_partial[(size_t)row0 * PARTS + pidx]       = rs0;
            g_partial[(size_t)(row0 + 8) * PARTS + pidx] = rs1;
        }
    }
}

// ---------------- K2: stats (partials reduce + gather) ----------------
__global__ void __launch_bounds__(256)
stats_kernel(const float* __restrict__ attn,
             const void* __restrict__ src_raw,
             const void* __restrict__ alignment_raw)
{
    __shared__ float red[256];
    const int b   = blockIdx.x;
    const int tid = threadIdx.x;

    float s = 0.f;
    for (int i = tid; i < PARTS; i += 256) s += g_partial[(size_t)b * PARTS + i];
    red[tid] = s; __syncthreads();
    for (int st = 128; st > 0; st >>= 1) {
        if (tid < st) red[tid] += red[tid + st];
        __syncthreads();
    }
    const float Sraw = red[0];
    __syncthreads();

    const float l4 = __half2float(g_logits[(size_t)b * V_DIM + COPY_IDX]);
    const float Z  = Sraw - __expf(l4) + 1.0f;           // exp(1e-10) == 1.0f
    const float copy = 1.f / (1.f + __expf(-l4));

    const bool src64 = detect_i64((const int*)src_raw);
    const bool aln64 = detect_i64((const int*)alignment_raw);

    float av = 0.f, a0 = 0.f;
    if (tid < S_DIM) {
        const size_t sidx = (size_t)b * S_DIM + tid;
        long long sv;
        if (src64) sv = ((const long long*)src_raw)[sidx];
        else       sv = (long long)((const int*)src_raw)[sidx];
        int tg;
        if (aln64) tg = (int)((const long long*)alignment_raw)[sv];
        else       tg = ((const int*)alignment_raw)[sv];
        g_tgt[b * S_DIM + tid] = tg;
        const float a = attn[sidx];
        g_addval[b * S_DIM + tid] = a * copy;
        av = a;
        a0 = (tg == PAD_IDX) ? a : 0.f;
    }
    red[tid] = av; __syncthreads();
    for (int st = 128; st > 0; st >>= 1) {
        if (tid < st) red[tid] += red[tid + st];
        __syncthreads();
    }
    const float sumattn = red[0];
    __syncthreads();
    red[tid] = a0; __syncthreads();
    for (int st = 128; st > 0; st >>= 1) {
        if (tid < st) red[tid] += red[tid + st];
        __syncthreads();
    }
    const float scat0 = red[0];

    if (tid == 0) {
        const float l0 = __half2float(g_logits[(size_t)b * V_DIM + PAD_IDX]);
        const float prepad = (1.f - copy) * __expf(l0) / Z + copy * scat0;
        const float norm = (1.f - copy) + copy * sumattn - prepad + EPS_F;
        g_stats[b] = make_float4(0.f, 1.f / Z, copy, 1.f / norm);
    }
}

// ---------------- K3: streaming log-prob:  out = log(k) + logit ----------------
// Round-8 structure exactly; only the logits read is cache-streaming (__ldcs)
// since it is touched exactly once while 205MB of writes compete for L2.
#define K3_SPLIT 8
__global__ void __launch_bounds__(256)
final_stream_kernel(float* __restrict__ out)
{
    const int b = blockIdx.x;
    const float4 st = g_stats[b];
    const float invZ = st.y, copy = st.z, invnorm = st.w;
    const float logk = __logf((1.f - copy) * invZ * invnorm);
    const uint4* in8 = (const uint4*)(g_logits + (size_t)b * V_DIM);  // 8 halves each
    float4* out4 = (float4*)(out + (size_t)b * V_DIM);
    const int NV8 = V_DIM / 8;                 // 6250
    const int per = (NV8 + K3_SPLIT - 1) / K3_SPLIT;
    const int beg = blockIdx.y * per;
    const int end = (beg + per < NV8) ? beg + per : NV8;
    for (int i = beg + threadIdx.x; i < end; i += 256) {
        const uint4 u = __ldcs(&in8[i]);
        const float2 p0 = __half22float2(*(const __half2*)&u.x);
        const float2 p1 = __half22float2(*(const __half2*)&u.y);
        float2 p2 = __half22float2(*(const __half2*)&u.z);
        const float2 p3 = __half22float2(*(const __half2*)&u.w);
        if (i == 0) p2.x = 1e-10f;             // COPY (element 4)
        float4 r0, r1;
        r0.x = logk + p0.x;
        r0.y = logk + p0.y;
        r0.z = logk + p1.x;
        r0.w = logk + p1.y;
        r1.x = logk + p2.x;
        r1.y = logk + p2.y;
        r1.z = logk + p3.x;
        r1.w = logk + p3.y;
        if (i == 0) r0.x = __logf(EPS_F * invnorm + EPS_F);   // PAD (exact)
        __stcs(&out4[2 * i],     r0);
        __stcs(&out4[2 * i + 1], r1);
    }
}

// ---------------- K4: scatter fixup (<=128 positions/row, dup-aggregating) --
__global__ void __launch_bounds__(128)
fixup_kernel(float* __restrict__ out)
{
    __shared__ int   stg[S_DIM];
    __shared__ float sad[S_DIM];
    const int b = blockIdx.x, t = threadIdx.x;
    stg[t] = g_tgt[b * S_DIM + t];
    sad[t] = g_addval[b * S_DIM + t];
    __syncthreads();
    const int tg = stg[t];
    if (tg == PAD_IDX) return;
    float tot = 0.f; bool first = true;
    for (int j = 0; j < S_DIM; ++j) {
        if (stg[j] == tg) { tot += sad[j]; if (j < t) first = false; }
    }
    if (!first) return;
    const float4 st = g_stats[b];
    const float l = (tg == COPY_IDX) ? 1e-10f
                                     : __half2float(g_logits[(size_t)b * V_DIM + tg]);
    const float p = (1.f - st.z) * st.y * __expf(l) + tot;
    out[(size_t)b * V_DIM + tg] = __logf(p * st.w + EPS_F);
}

// ---------------- launch ----------------
extern "C" void kernel_launch(void* const* d_in, const int* in_sizes, int n_in,
                              void* d_out, int out_size)
{
    const float* hidden    = (const float*)d_in[0];
    const void*  src       = d_in[1];
    const float* attn      = (const float*)d_in[2];
    const float* W         = (const float*)d_in[3];
    const float* bias      = (const float*)d_in[4];
    const void*  alignment = d_in[5];
    float*       out       = (float*)d_out;

    cudaFuncSetAttribute(gemm_kernel, cudaFuncAttributeMaxDynamicSharedMemorySize, SMEM_BYTES);

    convert_kernel<<<1184, 256>>>(W, hidden);

    dim3 g1(B_DIM / TM, NBLKS);                  // (8, 196) — M fastest for W L2 reuse
    gemm_kernel<<<g1, 256, SMEM_BYTES>>>(bias);

    stats_kernel<<<B_DIM, 256>>>(attn, src, alignment);

    dim3 g3(B_DIM, K3_SPLIT);
    final_stream_kernel<<<g3, 256>>>(out);

    fixup_kernel<<<B_DIM, S_DIM>>>(out);
}